// round 2
// baseline (speedup 1.0000x reference)
#include <cuda_runtime.h>
#include <cuda_bf16.h>
#include <cstdint>

// ---------------------------------------------------------------------------
// TalkingHeadAttention: B=4, N=1024, C=768, H=12, d=64
//   K1: qkv = x @ W_qkv + b_qkv   (q columns pre-scaled by d^-0.5 = 0.125)
//   K2: logits[b,h,n,m] = q_h[n] . k_h[m]
//   K3: fused  mix(W_l)+b_l -> softmax(m) -> mix(W_w)+b_w  -> attn (output 2)
//   K4: ctx[b,n,h,d] = sum_m attn[b,h,n,m] * v[b,h,m,d]
//   K5: out = ctx @ W_proj + b_proj                        -> out (output 1)
// d_out layout: [ out (4096*768) | attn (4*12*1024*1024) ]
// ---------------------------------------------------------------------------

#define BATCH 4
#define SEQ   1024
#define CDIM  768
#define HEADS 12
#define HDIM  64
#define QKVC  2304           // 3*CDIM
#define TOKS  4096           // BATCH*SEQ
#define OUT_ELEMS (TOKS * CDIM)

// Scratch (device globals: allocation-free, graph-capture safe)
__device__ float g_qkv[TOKS * QKVC];                          // ~37.7 MB
__device__ float g_logits[(size_t)BATCH * HEADS * SEQ * SEQ]; // ~201 MB
__device__ float g_ctx[TOKS * CDIM];                          // ~12.6 MB

// ---------------------------------------------------------------------------
// K1/K5: SGEMM  C[M,N] = A[M,K] @ B[K,N] + bias[N]
// 128x128x8 tile, 256 threads, 8x8 microtile. Dims divide tiles exactly.
// QSCALE: multiply columns < CDIM by 0.125 (q pre-scale) after bias.
// ---------------------------------------------------------------------------
template <bool QSCALE>
__global__ __launch_bounds__(256)
void sgemm_bias_kernel(const float* __restrict__ A,
                       const float* __restrict__ B,
                       const float* __restrict__ bias,
                       float* __restrict__ C,
                       int M, int Nn, int K)
{
    constexpr int BM = 128, BN = 128, BK = 8, TM = 8, TN = 8;
    __shared__ float As[BK][BM];
    __shared__ float Bs[BK][BN];

    const int tid = threadIdx.x;
    const int tx = tid & 15;
    const int ty = tid >> 4;
    const int row0 = blockIdx.y * BM;
    const int col0 = blockIdx.x * BN;

    const int aRow = tid >> 1;
    const int aCol = (tid & 1) * 4;
    const int bRow = tid >> 5;
    const int bCol = (tid & 31) * 4;

    float acc[TM][TN] = {};

    for (int k0 = 0; k0 < K; k0 += BK) {
        float4 av = *(const float4*)&A[(size_t)(row0 + aRow) * K + k0 + aCol];
        As[aCol + 0][aRow] = av.x;
        As[aCol + 1][aRow] = av.y;
        As[aCol + 2][aRow] = av.z;
        As[aCol + 3][aRow] = av.w;
        *(float4*)&Bs[bRow][bCol] =
            *(const float4*)&B[(size_t)(k0 + bRow) * Nn + col0 + bCol];
        __syncthreads();

#pragma unroll
        for (int kk = 0; kk < BK; kk++) {
            float ra[TM], rb[TN];
#pragma unroll
            for (int i = 0; i < TM; i++) ra[i] = As[kk][ty * TM + i];
#pragma unroll
            for (int j = 0; j < TN; j++) rb[j] = Bs[kk][tx * TN + j];
#pragma unroll
            for (int i = 0; i < TM; i++)
#pragma unroll
                for (int j = 0; j < TN; j++)
                    acc[i][j] = fmaf(ra[i], rb[j], acc[i][j]);
        }
        __syncthreads();
    }

    const int cbase = col0 + tx * TN;
#pragma unroll
    for (int i = 0; i < TM; i++) {
        const int r = row0 + ty * TM + i;
        float v[TN];
#pragma unroll
        for (int j = 0; j < TN; j++) {
            v[j] = acc[i][j] + bias[cbase + j];
            if (QSCALE && (cbase + j) < CDIM) v[j] *= 0.125f;
        }
        *(float4*)&C[(size_t)r * Nn + cbase]     = make_float4(v[0], v[1], v[2], v[3]);
        *(float4*)&C[(size_t)r * Nn + cbase + 4] = make_float4(v[4], v[5], v[6], v[7]);
    }
}

// ---------------------------------------------------------------------------
// K2: logits[bh, n, m] = sum_d q[b,n,h,d] * k[b,m,h,d]
// Per (b,h): [1024x64] @ [64x1024]^T. 128x128 tile, BK=16, 256 thr, 8x8.
// ---------------------------------------------------------------------------
__global__ __launch_bounds__(256)
void qk_logits_kernel(const float* __restrict__ qkv, float* __restrict__ logits)
{
    constexpr int BM = 128, BN = 128, BK = 16, TM = 8, TN = 8;
    __shared__ float As[BK][BM];
    __shared__ float Bs[BK][BN];

    const int tid = threadIdx.x;
    const int tx = tid & 15;
    const int ty = tid >> 4;
    const int bz = blockIdx.z;           // b*12 + h
    const int b = bz / HEADS;
    const int h = bz % HEADS;
    const int n0 = blockIdx.y * BM;
    const int m0 = blockIdx.x * BN;

    const float* qbase = qkv + (size_t)b * SEQ * QKVC + h * HDIM;
    const float* kbase = qkv + (size_t)b * SEQ * QKVC + CDIM + h * HDIM;

    float acc[TM][TN] = {};

    for (int k0 = 0; k0 < HDIM; k0 += BK) {
#pragma unroll
        for (int l = 0; l < 2; l++) {
            const int idx = tid + l * 256;
            const int r = idx >> 2;
            const int cg = (idx & 3) * 4;
            float4 av = *(const float4*)&qbase[(size_t)(n0 + r) * QKVC + k0 + cg];
            As[cg + 0][r] = av.x; As[cg + 1][r] = av.y;
            As[cg + 2][r] = av.z; As[cg + 3][r] = av.w;
            float4 bv = *(const float4*)&kbase[(size_t)(m0 + r) * QKVC + k0 + cg];
            Bs[cg + 0][r] = bv.x; Bs[cg + 1][r] = bv.y;
            Bs[cg + 2][r] = bv.z; Bs[cg + 3][r] = bv.w;
        }
        __syncthreads();

#pragma unroll
        for (int kk = 0; kk < BK; kk++) {
            float ra[TM], rb[TN];
#pragma unroll
            for (int i = 0; i < TM; i++) ra[i] = As[kk][ty * TM + i];
#pragma unroll
            for (int j = 0; j < TN; j++) rb[j] = Bs[kk][tx * TN + j];
#pragma unroll
            for (int i = 0; i < TM; i++)
#pragma unroll
                for (int j = 0; j < TN; j++)
                    acc[i][j] = fmaf(ra[i], rb[j], acc[i][j]);
        }
        __syncthreads();
    }

    float* obase = logits + (size_t)bz * SEQ * SEQ;
    const int cbase = m0 + tx * TN;
#pragma unroll
    for (int i = 0; i < TM; i++) {
        const int n = n0 + ty * TM + i;
        *(float4*)&obase[(size_t)n * SEQ + cbase] =
            make_float4(acc[i][0], acc[i][1], acc[i][2], acc[i][3]);
        *(float4*)&obase[(size_t)n * SEQ + cbase + 4] =
            make_float4(acc[i][4], acc[i][5], acc[i][6], acc[i][7]);
    }
}

// ---------------------------------------------------------------------------
// K3 (register-resident): per (b,n) row-block across all 12 heads:
//   mixed = W_l^T . logits + b_l ; p = softmax_m(mixed) ; attn = W_w^T . p + b_w
// One block per (b,n), 256 threads; thread t owns m = 4t..4t+3 (float4).
// Only small static smem (weights + reduction scratch). No dynamic smem.
// ---------------------------------------------------------------------------
__global__ __launch_bounds__(256)
void mix_softmax_kernel(const float* __restrict__ logits,
                        const float* __restrict__ W_l, const float* __restrict__ b_l,
                        const float* __restrict__ W_w, const float* __restrict__ b_w,
                        float* __restrict__ attn_out)
{
    __shared__ float swl[HEADS * HEADS], sww[HEADS * HEADS];
    __shared__ float sbl[HEADS], sbw[HEADS];
    __shared__ float red[HEADS][8];

    const int tid  = threadIdx.x;
    const int lane = tid & 31;
    const int warp = tid >> 5;
    const int bn = blockIdx.x;
    const int b = bn >> 10;
    const int n = bn & (SEQ - 1);

    if (tid < HEADS * HEADS) { swl[tid] = W_l[tid]; sww[tid] = W_w[tid]; }
    if (tid < HEADS) { sbl[tid] = b_l[tid]; sbw[tid] = b_w[tid]; }
    __syncthreads();

    // Load this thread's 4 m-columns for all 12 heads (coalesced float4).
    const float* lb = logits + ((size_t)b * HEADS * SEQ + n) * SEQ + tid * 4;
    float4 l[HEADS];
#pragma unroll
    for (int h = 0; h < HEADS; h++)
        l[h] = *(const float4*)&lb[(size_t)h * SEQ * SEQ];

    // mix1: m1[k] = b_l[k] + sum_h l[h] * W_l[h][k]
    float4 m1[HEADS];
#pragma unroll
    for (int k = 0; k < HEADS; k++) {
        float bk = sbl[k];
        float4 a = make_float4(bk, bk, bk, bk);
#pragma unroll
        for (int h = 0; h < HEADS; h++) {
            const float w = swl[h * HEADS + k];
            a.x = fmaf(l[h].x, w, a.x);
            a.y = fmaf(l[h].y, w, a.y);
            a.z = fmaf(l[h].z, w, a.z);
            a.w = fmaf(l[h].w, w, a.w);
        }
        m1[k] = a;
    }

    // ---- block max per k ----
    float rowmax[HEADS];
#pragma unroll
    for (int k = 0; k < HEADS; k++) {
        float v = fmaxf(fmaxf(m1[k].x, m1[k].y), fmaxf(m1[k].z, m1[k].w));
#pragma unroll
        for (int o = 16; o > 0; o >>= 1) v = fmaxf(v, __shfl_xor_sync(0xffffffff, v, o));
        if (lane == 0) red[k][warp] = v;
    }
    __syncthreads();
#pragma unroll
    for (int k = 0; k < HEADS; k++) {
        float v = red[k][0];
#pragma unroll
        for (int w = 1; w < 8; w++) v = fmaxf(v, red[k][w]);
        rowmax[k] = v;
    }
    __syncthreads();   // red reused below

    // ---- exp + block sum per k ----
    float inv[HEADS];
#pragma unroll
    for (int k = 0; k < HEADS; k++) {
        m1[k].x = __expf(m1[k].x - rowmax[k]);
        m1[k].y = __expf(m1[k].y - rowmax[k]);
        m1[k].z = __expf(m1[k].z - rowmax[k]);
        m1[k].w = __expf(m1[k].w - rowmax[k]);
        float s = (m1[k].x + m1[k].y) + (m1[k].z + m1[k].w);
#pragma unroll
        for (int o = 16; o > 0; o >>= 1) s += __shfl_xor_sync(0xffffffff, s, o);
        if (lane == 0) red[k][warp] = s;
    }
    __syncthreads();
#pragma unroll
    for (int k = 0; k < HEADS; k++) {
        float s = red[k][0];
#pragma unroll
        for (int w = 1; w < 8; w++) s += red[k][w];
        inv[k] = 1.0f / s;
    }

    // normalize in place: p[h] = m1[h] * inv[h]
#pragma unroll
    for (int h = 0; h < HEADS; h++) {
        m1[h].x *= inv[h]; m1[h].y *= inv[h];
        m1[h].z *= inv[h]; m1[h].w *= inv[h];
    }

    // mix2 + store: attn[b,k,n,m] = b_w[k] + sum_h p[h] * W_w[h][k]
    float* ob = attn_out + ((size_t)b * HEADS * SEQ + n) * SEQ + tid * 4;
#pragma unroll
    for (int k = 0; k < HEADS; k++) {
        float bk = sbw[k];
        float4 a = make_float4(bk, bk, bk, bk);
#pragma unroll
        for (int h = 0; h < HEADS; h++) {
            const float w = sww[h * HEADS + k];
            a.x = fmaf(m1[h].x, w, a.x);
            a.y = fmaf(m1[h].y, w, a.y);
            a.z = fmaf(m1[h].z, w, a.z);
            a.w = fmaf(m1[h].w, w, a.w);
        }
        *(float4*)&ob[(size_t)k * SEQ * SEQ] = a;
    }
}

// ---------------------------------------------------------------------------
// K4: ctx[b,n,h,d] = sum_m attn[b,h,n,m] * v[b,m,h,d]
// Per (b,h): [1024x1024]@[1024x64]. BM=128, BN=64, BK=32, 256 thr, 8x4.
// ---------------------------------------------------------------------------
__global__ __launch_bounds__(256)
void av_ctx_kernel(const float* __restrict__ attn,
                   const float* __restrict__ qkv,
                   float* __restrict__ ctx)
{
    constexpr int BM = 128, BN = 64, BK = 32, TM = 8, TN = 4;
    __shared__ float As[BK][BM];
    __shared__ float Bs[BK][BN];

    const int tid = threadIdx.x;
    const int tx = tid & 15;
    const int ty = tid >> 4;
    const int bz = blockIdx.z;
    const int b = bz / HEADS;
    const int h = bz % HEADS;
    const int n0 = blockIdx.y * BM;

    const float* abase = attn + (size_t)bz * SEQ * SEQ;
    const float* vbase = qkv + (size_t)b * SEQ * QKVC + 2 * CDIM + h * HDIM;

    float acc[TM][TN] = {};

    for (int k0 = 0; k0 < SEQ; k0 += BK) {
#pragma unroll
        for (int l = 0; l < 4; l++) {
            const int idx = tid + l * 256;
            const int r = idx >> 3;
            const int cg = (idx & 7) * 4;
            float4 av = *(const float4*)&abase[(size_t)(n0 + r) * SEQ + k0 + cg];
            As[cg + 0][r] = av.x; As[cg + 1][r] = av.y;
            As[cg + 2][r] = av.z; As[cg + 3][r] = av.w;
        }
#pragma unroll
        for (int l = 0; l < 2; l++) {
            const int idx = tid + l * 256;
            const int r = idx >> 4;
            const int cg = (idx & 15) * 4;
            *(float4*)&Bs[r][cg] = *(const float4*)&vbase[(size_t)(k0 + r) * QKVC + cg];
        }
        __syncthreads();

#pragma unroll
        for (int kk = 0; kk < BK; kk++) {
            float ra[TM], rb[TN];
#pragma unroll
            for (int i = 0; i < TM; i++) ra[i] = As[kk][ty * TM + i];
#pragma unroll
            for (int j = 0; j < TN; j++) rb[j] = Bs[kk][tx * TN + j];
#pragma unroll
            for (int i = 0; i < TM; i++)
#pragma unroll
                for (int j = 0; j < TN; j++)
                    acc[i][j] = fmaf(ra[i], rb[j], acc[i][j]);
        }
        __syncthreads();
    }

    const int dbase = h * HDIM + tx * TN;
#pragma unroll
    for (int i = 0; i < TM; i++) {
        const int n = n0 + ty * TM + i;
        *(float4*)&ctx[(size_t)(b * SEQ + n) * CDIM + dbase] =
            make_float4(acc[i][0], acc[i][1], acc[i][2], acc[i][3]);
    }
}

// ---------------------------------------------------------------------------
extern "C" void kernel_launch(void* const* d_in, const int* in_sizes, int n_in,
                              void* d_out, int out_size)
{
    const float* x      = (const float*)d_in[0];
    const float* W_qkv  = (const float*)d_in[1];
    const float* b_qkv  = (const float*)d_in[2];
    const float* W_l    = (const float*)d_in[3];
    const float* b_l    = (const float*)d_in[4];
    const float* W_w    = (const float*)d_in[5];
    const float* b_w    = (const float*)d_in[6];
    const float* W_proj = (const float*)d_in[7];
    const float* b_proj = (const float*)d_in[8];

    float* out  = (float*)d_out;
    float* attn = out + OUT_ELEMS;

    float *qkv_p, *logits_p, *ctx_p;
    cudaGetSymbolAddress((void**)&qkv_p, g_qkv);
    cudaGetSymbolAddress((void**)&logits_p, g_logits);
    cudaGetSymbolAddress((void**)&ctx_p, g_ctx);

    // K1: qkv = x @ W_qkv + b_qkv (q scaled)
    sgemm_bias_kernel<true><<<dim3(QKVC / 128, TOKS / 128), 256>>>(
        x, W_qkv, b_qkv, qkv_p, TOKS, QKVC, CDIM);

    // K2: logits
    qk_logits_kernel<<<dim3(SEQ / 128, SEQ / 128, BATCH * HEADS), 256>>>(
        qkv_p, logits_p);

    // K3: mix -> softmax -> mix -> attn output
    mix_softmax_kernel<<<TOKS, 256>>>(
        logits_p, W_l, b_l, W_w, b_w, attn);

    // K4: ctx = attn @ v
    av_ctx_kernel<<<dim3(1, SEQ / 128, BATCH * HEADS), 256>>>(
        attn, qkv_p, ctx_p);

    // K5: out = ctx @ W_proj + b_proj
    sgemm_bias_kernel<false><<<dim3(CDIM / 128, TOKS / 128), 256>>>(
        ctx_p, W_proj, b_proj, out, TOKS, CDIM, CDIM);
}

// round 3
// speedup vs baseline: 1.3653x; 1.3653x over previous
#include <cuda_runtime.h>
#include <cuda_bf16.h>
#include <mma.h>
#include <cstdint>

using namespace nvcuda;

// ---------------------------------------------------------------------------
// TalkingHeadAttention: B=4, N=1024, C=768, H=12, d=64
//   K1: qkv = x @ W_qkv + b_qkv   (q columns pre-scaled by 0.125)   [tf32 wmma]
//   K2: logits[b,h,n,m] = q_h[n] . k_h[m]                           [tf32 wmma]
//   K3: mix(W_l)+b_l -> softmax -> mix(W_w)+b_w -> attn (output 2)  [fp32]
//   K4: ctx[b,n,h,d] = sum_m attn[b,h,n,m] * v[b,m,h,d]             [tf32 wmma]
//   K5: out = ctx @ W_proj + b_proj          (output 1)             [tf32 wmma]
// d_out layout: [ out (4096*768) | attn (4*12*1024*1024) ]
// ---------------------------------------------------------------------------

#define BATCH 4
#define SEQ   1024
#define CDIM  768
#define HEADS 12
#define HDIM  64
#define QKVC  2304
#define TOKS  4096
#define OUT_ELEMS (TOKS * CDIM)

__device__ float g_qkv[TOKS * QKVC];                          // ~37.7 MB
__device__ float g_logits[(size_t)BATCH * HEADS * SEQ * SEQ]; // ~201 MB
__device__ float g_ctx[TOKS * CDIM];                          // ~12.6 MB

template <class Frag>
__device__ __forceinline__ void frag_to_tf32(Frag& f) {
#pragma unroll
    for (int i = 0; i < f.num_elements; i++)
        f.x[i] = wmma::__float_to_tf32(f.x[i]);
}

// ---------------------------------------------------------------------------
// K1/K5: tf32 wmma GEMM  C[M,N] = A[M,K] @ B[K,N] + bias[N]
// BM=128 BN=128 BK=16, 256 thr = 8 warps (2x4), warp tile 64x32 (4x2 frags).
// ---------------------------------------------------------------------------
template <bool QSCALE>
__global__ __launch_bounds__(256)
void wmma_gemm_bias(const float* __restrict__ A,
                    const float* __restrict__ B,
                    const float* __restrict__ bias,
                    float* __restrict__ C,
                    int M, int Nn, int K)
{
    constexpr int BM = 128, BN = 128, BK = 16;
    constexpr int LDA = BK + 8;    // 24
    constexpr int LDB = BN + 8;    // 136
    __shared__ __align__(16) float As[BM][LDA];
    __shared__ __align__(16) float Bs[BK][LDB];
    __shared__ __align__(16) float epi[8][256];

    const int tid  = threadIdx.x;
    const int warp = tid >> 5;
    const int lane = tid & 31;
    const int wm = warp & 1;       // 2 warp-rows of 64
    const int wn = warp >> 1;      // 4 warp-cols of 32
    const int row0 = blockIdx.y * BM;
    const int col0 = blockIdx.x * BN;

    wmma::fragment<wmma::accumulator, 16, 16, 8, float> acc[4][2];
#pragma unroll
    for (int i = 0; i < 4; i++)
#pragma unroll
        for (int j = 0; j < 2; j++)
            wmma::fill_fragment(acc[i][j], 0.0f);

    for (int k0 = 0; k0 < K; k0 += BK) {
        // A tile 128x16 (512 float4, 2/thread)
#pragma unroll
        for (int l = 0; l < 2; l++) {
            const int idx = tid + l * 256;
            const int r = idx >> 2;
            const int cg = (idx & 3) * 4;
            *(float4*)&As[r][cg] = *(const float4*)&A[(size_t)(row0 + r) * K + k0 + cg];
        }
        // B tile 16x128 (512 float4, 2/thread)
#pragma unroll
        for (int l = 0; l < 2; l++) {
            const int idx = tid + l * 256;
            const int r = idx >> 5;
            const int cg = (idx & 31) * 4;
            *(float4*)&Bs[r][cg] = *(const float4*)&B[(size_t)(k0 + r) * Nn + col0 + cg];
        }
        __syncthreads();

#pragma unroll
        for (int ks = 0; ks < BK; ks += 8) {
            wmma::fragment<wmma::matrix_b, 16, 16, 8, wmma::precision::tf32, wmma::row_major> bf[2];
#pragma unroll
            for (int j = 0; j < 2; j++) {
                wmma::load_matrix_sync(bf[j], &Bs[ks][wn * 32 + j * 16], LDB);
                frag_to_tf32(bf[j]);
            }
#pragma unroll
            for (int i = 0; i < 4; i++) {
                wmma::fragment<wmma::matrix_a, 16, 16, 8, wmma::precision::tf32, wmma::row_major> af;
                wmma::load_matrix_sync(af, &As[wm * 64 + i * 16][ks], LDA);
                frag_to_tf32(af);
#pragma unroll
                for (int j = 0; j < 2; j++)
                    wmma::mma_sync(acc[i][j], af, bf[j], acc[i][j]);
            }
        }
        __syncthreads();
    }

    // epilogue via per-warp smem bounce; add bias (+qscale)
#pragma unroll
    for (int i = 0; i < 4; i++) {
#pragma unroll
        for (int j = 0; j < 2; j++) {
            wmma::store_matrix_sync(&epi[warp][0], acc[i][j], 16, wmma::mem_row_major);
            __syncwarp();
            const int r  = lane >> 1;
            const int cg = (lane & 1) * 8;
            const int gr = row0 + wm * 64 + i * 16 + r;
            const int gc = col0 + wn * 32 + j * 16 + cg;
            float v[8];
#pragma unroll
            for (int e = 0; e < 8; e++) {
                v[e] = epi[warp][r * 16 + cg + e] + bias[gc + e];
                if (QSCALE && (gc + e) < CDIM) v[e] *= 0.125f;
            }
            *(float4*)&C[(size_t)gr * Nn + gc]     = make_float4(v[0], v[1], v[2], v[3]);
            *(float4*)&C[(size_t)gr * Nn + gc + 4] = make_float4(v[4], v[5], v[6], v[7]);
            __syncwarp();
        }
    }
}

// ---------------------------------------------------------------------------
// K2: tf32 wmma  logits[bh,n,m] = sum_d q[n,d] * k[m,d]   (B col-major)
// BM=BN=128 BK=16; per (b,h) K=64.
// ---------------------------------------------------------------------------
__global__ __launch_bounds__(256)
void wmma_qk(const float* __restrict__ qkv, float* __restrict__ logits)
{
    constexpr int BM = 128, BN = 128, BK = 16;
    constexpr int LDA = BK + 8;    // 24 (also B tile: [m][d] rows)
    __shared__ __align__(16) float As[BM][LDA];
    __shared__ __align__(16) float Bs[BN][LDA];
    __shared__ __align__(16) float epi[8][256];

    const int tid  = threadIdx.x;
    const int warp = tid >> 5;
    const int lane = tid & 31;
    const int wm = warp & 1;
    const int wn = warp >> 1;
    const int bz = blockIdx.z;            // b*HEADS + h
    const int b = bz / HEADS;
    const int h = bz % HEADS;
    const int n0 = blockIdx.y * BM;
    const int m0 = blockIdx.x * BN;

    const float* qbase = qkv + (size_t)b * SEQ * QKVC + h * HDIM;
    const float* kbase = qkv + (size_t)b * SEQ * QKVC + CDIM + h * HDIM;

    wmma::fragment<wmma::accumulator, 16, 16, 8, float> acc[4][2];
#pragma unroll
    for (int i = 0; i < 4; i++)
#pragma unroll
        for (int j = 0; j < 2; j++)
            wmma::fill_fragment(acc[i][j], 0.0f);

    for (int k0 = 0; k0 < HDIM; k0 += BK) {
#pragma unroll
        for (int l = 0; l < 2; l++) {
            const int idx = tid + l * 256;
            const int r = idx >> 2;
            const int cg = (idx & 3) * 4;
            *(float4*)&As[r][cg] = *(const float4*)&qbase[(size_t)(n0 + r) * QKVC + k0 + cg];
            *(float4*)&Bs[r][cg] = *(const float4*)&kbase[(size_t)(m0 + r) * QKVC + k0 + cg];
        }
        __syncthreads();

#pragma unroll
        for (int ks = 0; ks < BK; ks += 8) {
            // B col-major: element (d, m) at Bs[m][d]
            wmma::fragment<wmma::matrix_b, 16, 16, 8, wmma::precision::tf32, wmma::col_major> bf[2];
#pragma unroll
            for (int j = 0; j < 2; j++) {
                wmma::load_matrix_sync(bf[j], &Bs[wn * 32 + j * 16][ks], LDA);
                frag_to_tf32(bf[j]);
            }
#pragma unroll
            for (int i = 0; i < 4; i++) {
                wmma::fragment<wmma::matrix_a, 16, 16, 8, wmma::precision::tf32, wmma::row_major> af;
                wmma::load_matrix_sync(af, &As[wm * 64 + i * 16][ks], LDA);
                frag_to_tf32(af);
#pragma unroll
                for (int j = 0; j < 2; j++)
                    wmma::mma_sync(acc[i][j], af, bf[j], acc[i][j]);
            }
        }
        __syncthreads();
    }

    float* obase = logits + (size_t)bz * SEQ * SEQ;
#pragma unroll
    for (int i = 0; i < 4; i++) {
#pragma unroll
        for (int j = 0; j < 2; j++) {
            wmma::store_matrix_sync(&epi[warp][0], acc[i][j], 16, wmma::mem_row_major);
            __syncwarp();
            const int r  = lane >> 1;
            const int cg = (lane & 1) * 8;
            const int n  = n0 + wm * 64 + i * 16 + r;
            const int m  = m0 + wn * 32 + j * 16 + cg;
            *(float4*)&obase[(size_t)n * SEQ + m] =
                *(const float4*)&epi[warp][r * 16 + cg];
            *(float4*)&obase[(size_t)n * SEQ + m + 4] =
                *(const float4*)&epi[warp][r * 16 + cg + 4];
            __syncwarp();
        }
    }
}

// ---------------------------------------------------------------------------
// K3 (fp32, register-resident): per (b,n): mix1 -> softmax -> mix2 -> attn
// ---------------------------------------------------------------------------
__global__ __launch_bounds__(256)
void mix_softmax_kernel(const float* __restrict__ logits,
                        const float* __restrict__ W_l, const float* __restrict__ b_l,
                        const float* __restrict__ W_w, const float* __restrict__ b_w,
                        float* __restrict__ attn_out)
{
    __shared__ float swl[HEADS * HEADS], sww[HEADS * HEADS];
    __shared__ float sbl[HEADS], sbw[HEADS];
    __shared__ float red[HEADS][8];

    const int tid  = threadIdx.x;
    const int lane = tid & 31;
    const int warp = tid >> 5;
    const int bn = blockIdx.x;
    const int b = bn >> 10;
    const int n = bn & (SEQ - 1);

    if (tid < HEADS * HEADS) { swl[tid] = W_l[tid]; sww[tid] = W_w[tid]; }
    if (tid < HEADS) { sbl[tid] = b_l[tid]; sbw[tid] = b_w[tid]; }
    __syncthreads();

    const float* lb = logits + ((size_t)b * HEADS * SEQ + n) * SEQ + tid * 4;
    float4 l[HEADS];
#pragma unroll
    for (int h = 0; h < HEADS; h++)
        l[h] = *(const float4*)&lb[(size_t)h * SEQ * SEQ];

    float4 m1[HEADS];
#pragma unroll
    for (int k = 0; k < HEADS; k++) {
        float bk = sbl[k];
        float4 a = make_float4(bk, bk, bk, bk);
#pragma unroll
        for (int h = 0; h < HEADS; h++) {
            const float w = swl[h * HEADS + k];
            a.x = fmaf(l[h].x, w, a.x);
            a.y = fmaf(l[h].y, w, a.y);
            a.z = fmaf(l[h].z, w, a.z);
            a.w = fmaf(l[h].w, w, a.w);
        }
        m1[k] = a;
    }

    float rowmax[HEADS];
#pragma unroll
    for (int k = 0; k < HEADS; k++) {
        float v = fmaxf(fmaxf(m1[k].x, m1[k].y), fmaxf(m1[k].z, m1[k].w));
#pragma unroll
        for (int o = 16; o > 0; o >>= 1) v = fmaxf(v, __shfl_xor_sync(0xffffffff, v, o));
        if (lane == 0) red[k][warp] = v;
    }
    __syncthreads();
#pragma unroll
    for (int k = 0; k < HEADS; k++) {
        float v = red[k][0];
#pragma unroll
        for (int w = 1; w < 8; w++) v = fmaxf(v, red[k][w]);
        rowmax[k] = v;
    }
    __syncthreads();

    float inv[HEADS];
#pragma unroll
    for (int k = 0; k < HEADS; k++) {
        m1[k].x = __expf(m1[k].x - rowmax[k]);
        m1[k].y = __expf(m1[k].y - rowmax[k]);
        m1[k].z = __expf(m1[k].z - rowmax[k]);
        m1[k].w = __expf(m1[k].w - rowmax[k]);
        float s = (m1[k].x + m1[k].y) + (m1[k].z + m1[k].w);
#pragma unroll
        for (int o = 16; o > 0; o >>= 1) s += __shfl_xor_sync(0xffffffff, s, o);
        if (lane == 0) red[k][warp] = s;
    }
    __syncthreads();
#pragma unroll
    for (int k = 0; k < HEADS; k++) {
        float s = red[k][0];
#pragma unroll
        for (int w = 1; w < 8; w++) s += red[k][w];
        inv[k] = 1.0f / s;
    }

#pragma unroll
    for (int h = 0; h < HEADS; h++) {
        m1[h].x *= inv[h]; m1[h].y *= inv[h];
        m1[h].z *= inv[h]; m1[h].w *= inv[h];
    }

    float* ob = attn_out + ((size_t)b * HEADS * SEQ + n) * SEQ + tid * 4;
#pragma unroll
    for (int k = 0; k < HEADS; k++) {
        float bk = sbw[k];
        float4 a = make_float4(bk, bk, bk, bk);
#pragma unroll
        for (int h = 0; h < HEADS; h++) {
            const float w = sww[h * HEADS + k];
            a.x = fmaf(m1[h].x, w, a.x);
            a.y = fmaf(m1[h].y, w, a.y);
            a.z = fmaf(m1[h].z, w, a.z);
            a.w = fmaf(m1[h].w, w, a.w);
        }
        *(float4*)&ob[(size_t)k * SEQ * SEQ] = a;
    }
}

// ---------------------------------------------------------------------------
// K4: tf32 wmma  ctx[b,n,h,d] = sum_m attn[b,h,n,m] * v[b,m,h,d]
// BM=128 BN=64 BK=16; warps 4x2, warp tile 32x32 (2x2 frags).
// grid: (n-tiles=8, bh=48)
// ---------------------------------------------------------------------------
__global__ __launch_bounds__(256)
void wmma_av(const float* __restrict__ attn,
             const float* __restrict__ qkv,
             float* __restrict__ ctx)
{
    constexpr int BM = 128, BN = 64, BK = 16;
    constexpr int LDA = BK + 8;    // 24
    constexpr int LDB = BN + 8;    // 72
    __shared__ __align__(16) float As[BM][LDA];
    __shared__ __align__(16) float Bs[BK][LDB];
    __shared__ __align__(16) float epi[8][256];

    const int tid  = threadIdx.x;
    const int warp = tid >> 5;
    const int lane = tid & 31;
    const int wm = warp & 3;       // 4 warp-rows of 32
    const int wn = warp >> 2;      // 2 warp-cols of 32
    const int bz = blockIdx.y;
    const int b = bz / HEADS;
    const int h = bz % HEADS;
    const int n0 = blockIdx.x * BM;

    const float* abase = attn + (size_t)bz * SEQ * SEQ;
    const float* vbase = qkv + (size_t)b * SEQ * QKVC + 2 * CDIM + h * HDIM;

    wmma::fragment<wmma::accumulator, 16, 16, 8, float> acc[2][2];
#pragma unroll
    for (int i = 0; i < 2; i++)
#pragma unroll
        for (int j = 0; j < 2; j++)
            wmma::fill_fragment(acc[i][j], 0.0f);

    for (int k0 = 0; k0 < SEQ; k0 += BK) {
#pragma unroll
        for (int l = 0; l < 2; l++) {
            const int idx = tid + l * 256;
            const int r = idx >> 2;
            const int cg = (idx & 3) * 4;
            *(float4*)&As[r][cg] = *(const float4*)&abase[(size_t)(n0 + r) * SEQ + k0 + cg];
        }
        {
            const int r = tid >> 4;
            const int cg = (tid & 15) * 4;
            *(float4*)&Bs[r][cg] = *(const float4*)&vbase[(size_t)(k0 + r) * QKVC + cg];
        }
        __syncthreads();

#pragma unroll
        for (int ks = 0; ks < BK; ks += 8) {
            wmma::fragment<wmma::matrix_b, 16, 16, 8, wmma::precision::tf32, wmma::row_major> bf[2];
#pragma unroll
            for (int j = 0; j < 2; j++) {
                wmma::load_matrix_sync(bf[j], &Bs[ks][wn * 32 + j * 16], LDB);
                frag_to_tf32(bf[j]);
            }
#pragma unroll
            for (int i = 0; i < 2; i++) {
                wmma::fragment<wmma::matrix_a, 16, 16, 8, wmma::precision::tf32, wmma::row_major> af;
                wmma::load_matrix_sync(af, &As[wm * 32 + i * 16][ks], LDA);
                frag_to_tf32(af);
#pragma unroll
                for (int j = 0; j < 2; j++)
                    wmma::mma_sync(acc[i][j], af, bf[j], acc[i][j]);
            }
        }
        __syncthreads();
    }

#pragma unroll
    for (int i = 0; i < 2; i++) {
#pragma unroll
        for (int j = 0; j < 2; j++) {
            wmma::store_matrix_sync(&epi[warp][0], acc[i][j], 16, wmma::mem_row_major);
            __syncwarp();
            const int r  = lane >> 1;
            const int cg = (lane & 1) * 8;
            const int n  = n0 + wm * 32 + i * 16 + r;
            const int d  = h * HDIM + wn * 32 + j * 16 + cg;
            *(float4*)&ctx[(size_t)(b * SEQ + n) * CDIM + d] =
                *(const float4*)&epi[warp][r * 16 + cg];
            *(float4*)&ctx[(size_t)(b * SEQ + n) * CDIM + d + 4] =
                *(const float4*)&epi[warp][r * 16 + cg + 4];
            __syncwarp();
        }
    }
}

// ---------------------------------------------------------------------------
extern "C" void kernel_launch(void* const* d_in, const int* in_sizes, int n_in,
                              void* d_out, int out_size)
{
    const float* x      = (const float*)d_in[0];
    const float* W_qkv  = (const float*)d_in[1];
    const float* b_qkv  = (const float*)d_in[2];
    const float* W_l    = (const float*)d_in[3];
    const float* b_l    = (const float*)d_in[4];
    const float* W_w    = (const float*)d_in[5];
    const float* b_w    = (const float*)d_in[6];
    const float* W_proj = (const float*)d_in[7];
    const float* b_proj = (const float*)d_in[8];

    float* out  = (float*)d_out;
    float* attn = out + OUT_ELEMS;

    float *qkv_p, *logits_p, *ctx_p;
    cudaGetSymbolAddress((void**)&qkv_p, g_qkv);
    cudaGetSymbolAddress((void**)&logits_p, g_logits);
    cudaGetSymbolAddress((void**)&ctx_p, g_ctx);

    // K1: qkv = x @ W_qkv + b_qkv (q scaled)
    wmma_gemm_bias<true><<<dim3(QKVC / 128, TOKS / 128), 256>>>(
        x, W_qkv, b_qkv, qkv_p, TOKS, QKVC, CDIM);

    // K2: logits = q @ k^T per (b,h)
    wmma_qk<<<dim3(SEQ / 128, SEQ / 128, BATCH * HEADS), 256>>>(
        qkv_p, logits_p);

    // K3: mix -> softmax -> mix -> attn output
    mix_softmax_kernel<<<TOKS, 256>>>(
        logits_p, W_l, b_l, W_w, b_w, attn);

    // K4: ctx = attn @ v per (b,h)
    wmma_av<<<dim3(SEQ / 128, BATCH * HEADS), 256>>>(
        attn, qkv_p, ctx_p);

    // K5: out = ctx @ W_proj + b_proj
    wmma_gemm_bias<false><<<dim3(CDIM / 128, TOKS / 128), 256>>>(
        ctx_p, W_proj, b_proj, out, TOKS, CDIM, CDIM);
}

// round 5
// speedup vs baseline: 1.7511x; 1.2826x over previous
#include <cuda_runtime.h>
#include <cuda_fp16.h>
#include <cstdint>

// ---------------------------------------------------------------------------
// TalkingHeadAttention: B=4, N=1024, C=768, H=12, d=64
// fp16-split (3-term compensated) mma.sync GEMMs + fp32 softmax/mix.
// tcgen05 unavailable: harness compiles PTX for compute_100 (no 'a' features),
// so tensor work uses plain mma.sync.m16n8k16 (legacy HMMA path).
//   P1/P2: transpose W_qkv, W_proj -> [N][K] fp32
//   K1: qkv = x @ W_qkv + b_qkv (q cols pre-scaled 0.125)        [mma fp16x3]
//   P3: transpose v -> vt[bh][d][m]
//   K2: logits[bh,n,m] = q.k                                     [mma fp16x3]
//   K3: mix(W_l)+b_l -> softmax -> mix(W_w)+b_w -> attn (out 2)  [fp32]
//   K4: ctx = attn @ v                                           [mma fp16x3]
//   K5: out = ctx @ W_proj + b_proj (out 1)                      [mma fp16x3]
// d_out layout: [ out (4096*768) | attn (4*12*1024*1024) ]
// ---------------------------------------------------------------------------

#define BATCH 4
#define SEQ   1024
#define CDIM  768
#define HEADS 12
#define HDIM  64
#define QKVC  2304
#define TOKS  4096
#define OUT_ELEMS (TOKS * CDIM)

__device__ float g_qkv[TOKS * QKVC];                          // 37.7 MB
__device__ float g_logits[(size_t)BATCH * HEADS * SEQ * SEQ]; // 201 MB
__device__ float g_ctx[TOKS * CDIM];                          // 12.6 MB
__device__ float g_wqkvt[QKVC * CDIM];                        // [2304][768]
__device__ float g_wprojt[CDIM * CDIM];                       // [768][768]
__device__ float g_vt[(size_t)BATCH * HEADS * HDIM * SEQ];    // [bh][64][1024]

// ------------------------------ asm helpers --------------------------------
__device__ __forceinline__ uint32_t smem_to_u32(const void* p) {
    uint32_t a;
    asm("{ .reg .u64 t; cvta.to.shared.u64 t, %1; cvt.u32.u64 %0, t; }" : "=r"(a) : "l"(p));
    return a;
}
#define LDSM4(d0, d1, d2, d3, a) \
    asm volatile("ldmatrix.sync.aligned.m8n8.x4.shared.b16 {%0,%1,%2,%3}, [%4];" \
                 : "=r"(d0), "=r"(d1), "=r"(d2), "=r"(d3) : "r"(a))
#define MMA16816(c, a, b) \
    asm volatile("mma.sync.aligned.m16n8k16.row.col.f32.f16.f16.f32 " \
                 "{%0,%1,%2,%3}, {%4,%5,%6,%7}, {%8,%9}, {%0,%1,%2,%3};" \
                 : "+f"((c)[0]), "+f"((c)[1]), "+f"((c)[2]), "+f"((c)[3]) \
                 : "r"((a)[0]), "r"((a)[1]), "r"((a)[2]), "r"((a)[3]), \
                   "r"((b)[0]), "r"((b)[1]))

// split fp32 -> fp16 hi/lo, store 4 elems (8B each) into SW128-swizzled tile
__device__ __forceinline__ void split_store_h(float4 v, char* hi, char* lo, int off) {
    const int sw = off ^ ((off >> 3) & 0x70);
    __half hx = __float2half_rn(v.x), hy = __float2half_rn(v.y),
           hz = __float2half_rn(v.z), hw = __float2half_rn(v.w);
    uint32_t h0 = (uint32_t)__half_as_ushort(hx) | ((uint32_t)__half_as_ushort(hy) << 16);
    uint32_t h1 = (uint32_t)__half_as_ushort(hz) | ((uint32_t)__half_as_ushort(hw) << 16);
    *(uint2*)(hi + sw) = make_uint2(h0, h1);
    __half lx = __float2half_rn(v.x - __half2float(hx));
    __half ly = __float2half_rn(v.y - __half2float(hy));
    __half lz = __float2half_rn(v.z - __half2float(hz));
    __half lw = __float2half_rn(v.w - __half2float(hw));
    uint32_t l0 = (uint32_t)__half_as_ushort(lx) | ((uint32_t)__half_as_ushort(ly) << 16);
    uint32_t l1 = (uint32_t)__half_as_ushort(lz) | ((uint32_t)__half_as_ushort(lw) << 16);
    *(uint2*)(lo + sw) = make_uint2(l0, l1);
}

// ---------------------------------------------------------------------------
// GEMM: D[M,N] = A[M,K] . B[N,K]^T via fp16-split 3-term mma.sync.
// BM=128, BK=64. MODE: 0=K1 (bias+qscale), 1=K2, 2=K4 (BN=64), 3=K5 (bias).
// 256 threads = 8 warps. BN=128: warps 2x4 (64x32 tile). BN=64: 4x2 (32x32).
// smem per stage: Ah 16K | Al 16K | Bh BN*128 | Bl BN*128 (SW128 swizzle).
// ---------------------------------------------------------------------------
template <int MODE>
__global__ __launch_bounds__(256, 1)
void tc_gemm(const float* __restrict__ A, const float* __restrict__ B,
             const float* __restrict__ bias, float* __restrict__ C)
{
    constexpr int BN    = (MODE == 2) ? 64 : 128;
    constexpr int K_TOT = (MODE == 1) ? 64 : (MODE == 2) ? 1024 : 768;
    constexpr int LDA   = (MODE == 0) ? CDIM : (MODE == 1) ? QKVC : (MODE == 2) ? SEQ : CDIM;
    constexpr int LDB   = (MODE == 1) ? QKVC : (MODE == 2) ? SEQ : CDIM;
    constexpr int LDC   = (MODE == 0) ? QKVC : (MODE == 1) ? SEQ : CDIM;
    constexpr int NITER = K_TOT / 64;
    constexpr int WM    = (MODE == 2) ? 2 : 4;      // m16 frags per warp
    constexpr int AREG  = 8;                         // float4 per thread (A tile)
    constexpr int BREG  = BN / 16;                   // float4 per thread (B tile)
    constexpr int OFF_AL = 16384;
    constexpr int OFF_BH = 32768;
    constexpr int OFF_BL = 32768 + BN * 128;
    constexpr int STAGE  = 32768 + 2 * BN * 128;

    extern __shared__ char smem[];
    const uint32_t smem_base = smem_to_u32(smem);
    const int tid  = threadIdx.x;
    const int warp = tid >> 5;
    const int lane = tid & 31;
    const int wmBase = (MODE == 2) ? (warp >> 1) * 32 : (warp & 1) * 64;
    const int wnBase = (MODE == 2) ? (warp & 1) * 32 : (warp >> 1) * 32;

    const int row0 = blockIdx.y * 128;
    const int col0 = blockIdx.x * BN;
    const int z = blockIdx.z;

    size_t aOff = 0, bOff = 0, cOff = 0;
    if (MODE == 1) {
        const int b = z / HEADS, h = z % HEADS;
        aOff = (size_t)b * SEQ * QKVC + (size_t)h * HDIM;
        bOff = aOff + CDIM;
        cOff = (size_t)z * SEQ * SEQ;
    } else if (MODE == 2) {
        aOff = (size_t)z * SEQ * SEQ;
        bOff = (size_t)z * HDIM * SEQ;
        cOff = (size_t)(z / HEADS) * SEQ * CDIM + (size_t)(z % HEADS) * HDIM;
    }
    const float* Ap = A + aOff;
    const float* Bp = B + bOff;
    float* Cp = C + cOff;

    float acc[WM][4][4];
#pragma unroll
    for (int i = 0; i < WM; i++)
#pragma unroll
        for (int j = 0; j < 4; j++)
#pragma unroll
            for (int e = 0; e < 4; e++) acc[i][j][e] = 0.0f;

    float4 aR[AREG], bR[BREG];

    auto load_gmem = [&](int k0) {
#pragma unroll
        for (int l = 0; l < AREG; l++) {
            const int g = tid + l * 256;
            aR[l] = *(const float4*)&Ap[(size_t)(row0 + (g >> 4)) * LDA + k0 + (g & 15) * 4];
        }
#pragma unroll
        for (int l = 0; l < BREG; l++) {
            const int g = tid + l * 256;
            bR[l] = *(const float4*)&Bp[(size_t)(col0 + (g >> 4)) * LDB + k0 + (g & 15) * 4];
        }
    };
    auto store_smem = [&](int p) {
        char* base = smem + p * STAGE;
#pragma unroll
        for (int l = 0; l < AREG; l++) {
            const int g = tid + l * 256;
            split_store_h(aR[l], base, base + OFF_AL, (g >> 4) * 128 + (g & 15) * 8);
        }
#pragma unroll
        for (int l = 0; l < BREG; l++) {
            const int g = tid + l * 256;
            split_store_h(bR[l], base + OFF_BH, base + OFF_BL, (g >> 4) * 128 + (g & 15) * 8);
        }
    };
    auto compute = [&](int p, int kkBeg, int kkEnd) {
        const uint32_t sb = smem_base + p * STAGE;
        const int r = lane & 7, g = lane >> 3;
        for (int kk = kkBeg; kk < kkEnd; kk++) {
            uint32_t ah[WM][4], al[WM][4];
#pragma unroll
            for (int i = 0; i < WM; i++) {
                const int row = wmBase + i * 16 + (g & 1) * 8 + r;
                int off = row * 128 + kk * 32 + (g >> 1) * 16;
                off ^= (off >> 3) & 0x70;
                LDSM4(ah[i][0], ah[i][1], ah[i][2], ah[i][3], sb + off);
                LDSM4(al[i][0], al[i][1], al[i][2], al[i][3], sb + OFF_AL + off);
            }
            uint32_t bh[4][2], bl[4][2];
#pragma unroll
            for (int jp = 0; jp < 2; jp++) {
                const int n = wnBase + jp * 16 + (g >> 1) * 8 + r;
                int off = n * 128 + kk * 32 + (g & 1) * 16;
                off ^= (off >> 3) & 0x70;
                LDSM4(bh[2 * jp][0], bh[2 * jp][1], bh[2 * jp + 1][0], bh[2 * jp + 1][1],
                      sb + OFF_BH + off);
                LDSM4(bl[2 * jp][0], bl[2 * jp][1], bl[2 * jp + 1][0], bl[2 * jp + 1][1],
                      sb + OFF_BL + off);
            }
#pragma unroll
            for (int i = 0; i < WM; i++)
#pragma unroll
                for (int j = 0; j < 4; j++) {
                    MMA16816(acc[i][j], ah[i], bh[j]);
                    MMA16816(acc[i][j], ah[i], bl[j]);
                    MMA16816(acc[i][j], al[i], bh[j]);
                }
        }
    };

    load_gmem(0);
    store_smem(0);
    __syncthreads();

    for (int it = 0; it < NITER; it++) {
        const int p = it & 1;
        const bool more = (it + 1 < NITER);
        if (more) load_gmem((it + 1) * 64);
        compute(p, 0, 2);
        if (more) store_smem(p ^ 1);
        compute(p, 2, 4);
        __syncthreads();
    }

    // epilogue: acc -> gmem fp32 (+bias, +qscale)
    const int qr = lane >> 2;            // 0..7
    const int qc = (lane & 3) * 2;       // 0,2,4,6
#pragma unroll
    for (int i = 0; i < WM; i++) {
#pragma unroll
        for (int j = 0; j < 4; j++) {
            const int gr = row0 + wmBase + i * 16 + qr;
            const int gc = col0 + wnBase + j * 8 + qc;
            float v0 = acc[i][j][0], v1 = acc[i][j][1];
            float v2 = acc[i][j][2], v3 = acc[i][j][3];
            if (MODE == 0 || MODE == 3) {
                const float b0 = bias[gc], b1 = bias[gc + 1];
                v0 += b0; v1 += b1; v2 += b0; v3 += b1;
            }
            if (MODE == 0) {
                if (gc < CDIM)     { v0 *= 0.125f; v2 *= 0.125f; }
                if (gc + 1 < CDIM) { v1 *= 0.125f; v3 *= 0.125f; }
            }
            *(float2*)&Cp[(size_t)gr * LDC + gc]       = make_float2(v0, v1);
            *(float2*)&Cp[(size_t)(gr + 8) * LDC + gc] = make_float2(v2, v3);
        }
    }
}

// ---------------------------------------------------------------------------
// Transposes (fp32)
// ---------------------------------------------------------------------------
__global__ void transpose_k(const float* __restrict__ in, float* __restrict__ out,
                            int rows, int cols)
{
    __shared__ float t[32][33];
    const int x = blockIdx.x * 32 + threadIdx.x;
    const int y0 = blockIdx.y * 32;
#pragma unroll
    for (int j = threadIdx.y; j < 32; j += 8)
        t[j][threadIdx.x] = in[(size_t)(y0 + j) * cols + x];
    __syncthreads();
    const int x2 = y0 + threadIdx.x;
    const int y2 = blockIdx.x * 32;
#pragma unroll
    for (int j = threadIdx.y; j < 32; j += 8)
        out[(size_t)(y2 + j) * rows + x2] = t[threadIdx.x][j];
}

__global__ void vt_kernel(const float* __restrict__ qkv, float* __restrict__ vt)
{
    __shared__ float t[32][33];
    const int z = blockIdx.z;
    const int b = z / HEADS, h = z % HEADS;
    const float* in = qkv + (size_t)b * SEQ * QKVC + 2 * CDIM + (size_t)h * HDIM;
    const int m0 = blockIdx.x * 32, d0 = blockIdx.y * 32;
#pragma unroll
    for (int j = threadIdx.y; j < 32; j += 8)
        t[j][threadIdx.x] = in[(size_t)(m0 + j) * QKVC + d0 + threadIdx.x];
    __syncthreads();
    float* outp = vt + (size_t)z * HDIM * SEQ;
#pragma unroll
    for (int j = threadIdx.y; j < 32; j += 8)
        outp[(size_t)(d0 + j) * SEQ + m0 + threadIdx.x] = t[threadIdx.x][j];
}

// ---------------------------------------------------------------------------
// K3 (fp32, register-resident): per (b,n): mix1 -> softmax -> mix2 -> attn
// ---------------------------------------------------------------------------
__global__ __launch_bounds__(256)
void mix_softmax_kernel(const float* __restrict__ logits,
                        const float* __restrict__ W_l, const float* __restrict__ b_l,
                        const float* __restrict__ W_w, const float* __restrict__ b_w,
                        float* __restrict__ attn_out)
{
    __shared__ float swl[HEADS * HEADS], sww[HEADS * HEADS];
    __shared__ float sbl[HEADS], sbw[HEADS];
    __shared__ float red[HEADS][8];

    const int tid  = threadIdx.x;
    const int lane = tid & 31;
    const int warp = tid >> 5;
    const int bn = blockIdx.x;
    const int b = bn >> 10;
    const int n = bn & (SEQ - 1);

    if (tid < HEADS * HEADS) { swl[tid] = W_l[tid]; sww[tid] = W_w[tid]; }
    if (tid < HEADS) { sbl[tid] = b_l[tid]; sbw[tid] = b_w[tid]; }
    __syncthreads();

    const float* lb = logits + ((size_t)b * HEADS * SEQ + n) * SEQ + tid * 4;
    float4 l[HEADS];
#pragma unroll
    for (int h = 0; h < HEADS; h++)
        l[h] = *(const float4*)&lb[(size_t)h * SEQ * SEQ];

    float4 m1[HEADS];
#pragma unroll
    for (int k = 0; k < HEADS; k++) {
        float bk = sbl[k];
        float4 a = make_float4(bk, bk, bk, bk);
#pragma unroll
        for (int h = 0; h < HEADS; h++) {
            const float w = swl[h * HEADS + k];
            a.x = fmaf(l[h].x, w, a.x);
            a.y = fmaf(l[h].y, w, a.y);
            a.z = fmaf(l[h].z, w, a.z);
            a.w = fmaf(l[h].w, w, a.w);
        }
        m1[k] = a;
    }

    float rowmax[HEADS];
#pragma unroll
    for (int k = 0; k < HEADS; k++) {
        float v = fmaxf(fmaxf(m1[k].x, m1[k].y), fmaxf(m1[k].z, m1[k].w));
#pragma unroll
        for (int o = 16; o > 0; o >>= 1) v = fmaxf(v, __shfl_xor_sync(0xffffffff, v, o));
        if (lane == 0) red[k][warp] = v;
    }
    __syncthreads();
#pragma unroll
    for (int k = 0; k < HEADS; k++) {
        float v = red[k][0];
#pragma unroll
        for (int w = 1; w < 8; w++) v = fmaxf(v, red[k][w]);
        rowmax[k] = v;
    }
    __syncthreads();

    float inv[HEADS];
#pragma unroll
    for (int k = 0; k < HEADS; k++) {
        m1[k].x = __expf(m1[k].x - rowmax[k]);
        m1[k].y = __expf(m1[k].y - rowmax[k]);
        m1[k].z = __expf(m1[k].z - rowmax[k]);
        m1[k].w = __expf(m1[k].w - rowmax[k]);
        float s = (m1[k].x + m1[k].y) + (m1[k].z + m1[k].w);
#pragma unroll
        for (int o = 16; o > 0; o >>= 1) s += __shfl_xor_sync(0xffffffff, s, o);
        if (lane == 0) red[k][warp] = s;
    }
    __syncthreads();
#pragma unroll
    for (int k = 0; k < HEADS; k++) {
        float s = red[k][0];
#pragma unroll
        for (int w = 1; w < 8; w++) s += red[k][w];
        inv[k] = 1.0f / s;
    }

#pragma unroll
    for (int h = 0; h < HEADS; h++) {
        m1[h].x *= inv[h]; m1[h].y *= inv[h];
        m1[h].z *= inv[h]; m1[h].w *= inv[h];
    }

    float* ob = attn_out + ((size_t)b * HEADS * SEQ + n) * SEQ + tid * 4;
#pragma unroll
    for (int k = 0; k < HEADS; k++) {
        float bk = sbw[k];
        float4 a = make_float4(bk, bk, bk, bk);
#pragma unroll
        for (int h = 0; h < HEADS; h++) {
            const float w = sww[h * HEADS + k];
            a.x = fmaf(m1[h].x, w, a.x);
            a.y = fmaf(m1[h].y, w, a.y);
            a.z = fmaf(m1[h].z, w, a.z);
            a.w = fmaf(m1[h].w, w, a.w);
        }
        *(float4*)&ob[(size_t)k * SEQ * SEQ] = a;
    }
}

// ---------------------------------------------------------------------------
extern "C" void kernel_launch(void* const* d_in, const int* in_sizes, int n_in,
                              void* d_out, int out_size)
{
    const float* x      = (const float*)d_in[0];
    const float* W_qkv  = (const float*)d_in[1];
    const float* b_qkv  = (const float*)d_in[2];
    const float* W_l    = (const float*)d_in[3];
    const float* b_l    = (const float*)d_in[4];
    const float* W_w    = (const float*)d_in[5];
    const float* b_w    = (const float*)d_in[6];
    const float* W_proj = (const float*)d_in[7];
    const float* b_proj = (const float*)d_in[8];

    float* out  = (float*)d_out;
    float* attn = out + OUT_ELEMS;

    float *qkv_p, *logits_p, *ctx_p, *wqkvt_p, *wprojt_p, *vt_p;
    cudaGetSymbolAddress((void**)&qkv_p, g_qkv);
    cudaGetSymbolAddress((void**)&logits_p, g_logits);
    cudaGetSymbolAddress((void**)&ctx_p, g_ctx);
    cudaGetSymbolAddress((void**)&wqkvt_p, g_wqkvt);
    cudaGetSymbolAddress((void**)&wprojt_p, g_wprojt);
    cudaGetSymbolAddress((void**)&vt_p, g_vt);

    const int smemBig = 2 * (32768 + 2 * 128 * 128);  // 131072 (BN=128, 2 stages)
    const int smemK2  = 32768 + 2 * 128 * 128;        //  65536 (single chunk)
    const int smemK4  = 2 * (32768 + 2 * 64 * 128);   //  98304 (BN=64)
    cudaFuncSetAttribute(tc_gemm<0>, cudaFuncAttributeMaxDynamicSharedMemorySize, smemBig);
    cudaFuncSetAttribute(tc_gemm<1>, cudaFuncAttributeMaxDynamicSharedMemorySize, smemK2);
    cudaFuncSetAttribute(tc_gemm<2>, cudaFuncAttributeMaxDynamicSharedMemorySize, smemK4);
    cudaFuncSetAttribute(tc_gemm<3>, cudaFuncAttributeMaxDynamicSharedMemorySize, smemBig);

    // P1/P2: weight transposes -> [N][K]
    transpose_k<<<dim3(QKVC / 32, CDIM / 32), dim3(32, 8)>>>(W_qkv, wqkvt_p, CDIM, QKVC);
    transpose_k<<<dim3(CDIM / 32, CDIM / 32), dim3(32, 8)>>>(W_proj, wprojt_p, CDIM, CDIM);

    // K1: qkv = x @ W_qkv^T' + b (q scaled)
    tc_gemm<0><<<dim3(QKVC / 128, TOKS / 128, 1), 256, smemBig>>>(x, wqkvt_p, b_qkv, qkv_p);

    // P3: v transpose -> vt[bh][d][m]
    vt_kernel<<<dim3(SEQ / 32, HDIM / 32, BATCH * HEADS), dim3(32, 8)>>>(qkv_p, vt_p);

    // K2: logits = q @ k^T per (b,h)
    tc_gemm<1><<<dim3(SEQ / 128, SEQ / 128, BATCH * HEADS), 256, smemK2>>>(
        qkv_p, qkv_p, nullptr, logits_p);

    // K3: mix -> softmax -> mix -> attn output
    mix_softmax_kernel<<<TOKS, 256>>>(logits_p, W_l, b_l, W_w, b_w, attn);

    // K4: ctx = attn @ vt^T per (b,h)
    tc_gemm<2><<<dim3(1, SEQ / 128, BATCH * HEADS), 256, smemK4>>>(
        attn, vt_p, nullptr, ctx_p);

    // K5: out = ctx @ W_proj^T' + b
    tc_gemm<3><<<dim3(CDIM / 128, TOKS / 128, 1), 256, smemBig>>>(
        ctx_p, wprojt_p, b_proj, out);
}

// round 6
// speedup vs baseline: 1.7513x; 1.0001x over previous
#include <cuda_runtime.h>
#include <cuda_fp16.h>
#include <cstdint>

// ---------------------------------------------------------------------------
// TalkingHeadAttention: B=4, N=1024, C=768, H=12, d=64
// fp16-split (3-term compensated) mma.sync GEMMs + fp32 softmax/mix.
// tcgen05 unavailable (harness compiles for compute_100, no 'a' features).
// This round: term-major MMA issue order (breaks accumulator RAW chains).
//   P1/P2: transpose W_qkv, W_proj -> [N][K] fp32
//   K1: qkv = x @ W_qkv + b_qkv (q cols pre-scaled 0.125)        [mma fp16x3]
//   P3: transpose v -> vt[bh][d][m]
//   K2: logits[bh,n,m] = q.k                                     [mma fp16x3]
//   K3: mix(W_l)+b_l -> softmax -> mix(W_w)+b_w -> attn (out 2)  [fp32]
//   K4: ctx = attn @ v                                           [mma fp16x3]
//   K5: out = ctx @ W_proj + b_proj (out 1)                      [mma fp16x3]
// d_out layout: [ out (4096*768) | attn (4*12*1024*1024) ]
// ---------------------------------------------------------------------------

#define BATCH 4
#define SEQ   1024
#define CDIM  768
#define HEADS 12
#define HDIM  64
#define QKVC  2304
#define TOKS  4096
#define OUT_ELEMS (TOKS * CDIM)

__device__ float g_qkv[TOKS * QKVC];                          // 37.7 MB
__device__ float g_logits[(size_t)BATCH * HEADS * SEQ * SEQ]; // 201 MB
__device__ float g_ctx[TOKS * CDIM];                          // 12.6 MB
__device__ float g_wqkvt[QKVC * CDIM];                        // [2304][768]
__device__ float g_wprojt[CDIM * CDIM];                       // [768][768]
__device__ float g_vt[(size_t)BATCH * HEADS * HDIM * SEQ];    // [bh][64][1024]

// ------------------------------ asm helpers --------------------------------
__device__ __forceinline__ uint32_t smem_to_u32(const void* p) {
    uint32_t a;
    asm("{ .reg .u64 t; cvta.to.shared.u64 t, %1; cvt.u32.u64 %0, t; }" : "=r"(a) : "l"(p));
    return a;
}
#define LDSM4(d0, d1, d2, d3, a) \
    asm volatile("ldmatrix.sync.aligned.m8n8.x4.shared.b16 {%0,%1,%2,%3}, [%4];" \
                 : "=r"(d0), "=r"(d1), "=r"(d2), "=r"(d3) : "r"(a))
#define MMA16816(c, a, b) \
    asm volatile("mma.sync.aligned.m16n8k16.row.col.f32.f16.f16.f32 " \
                 "{%0,%1,%2,%3}, {%4,%5,%6,%7}, {%8,%9}, {%0,%1,%2,%3};" \
                 : "+f"((c)[0]), "+f"((c)[1]), "+f"((c)[2]), "+f"((c)[3]) \
                 : "r"((a)[0]), "r"((a)[1]), "r"((a)[2]), "r"((a)[3]), \
                   "r"((b)[0]), "r"((b)[1]))

// split fp32 -> fp16 hi/lo, store 4 elems (8B each) into SW128-swizzled tile
__device__ __forceinline__ void split_store_h(float4 v, char* hi, char* lo, int off) {
    const int sw = off ^ ((off >> 3) & 0x70);
    __half hx = __float2half_rn(v.x), hy = __float2half_rn(v.y),
           hz = __float2half_rn(v.z), hw = __float2half_rn(v.w);
    uint32_t h0 = (uint32_t)__half_as_ushort(hx) | ((uint32_t)__half_as_ushort(hy) << 16);
    uint32_t h1 = (uint32_t)__half_as_ushort(hz) | ((uint32_t)__half_as_ushort(hw) << 16);
    *(uint2*)(hi + sw) = make_uint2(h0, h1);
    __half lx = __float2half_rn(v.x - __half2float(hx));
    __half ly = __float2half_rn(v.y - __half2float(hy));
    __half lz = __float2half_rn(v.z - __half2float(hz));
    __half lw = __float2half_rn(v.w - __half2float(hw));
    uint32_t l0 = (uint32_t)__half_as_ushort(lx) | ((uint32_t)__half_as_ushort(ly) << 16);
    uint32_t l1 = (uint32_t)__half_as_ushort(lz) | ((uint32_t)__half_as_ushort(lw) << 16);
    *(uint2*)(lo + sw) = make_uint2(l0, l1);
}

// ---------------------------------------------------------------------------
// GEMM: D[M,N] = A[M,K] . B[N,K]^T via fp16-split 3-term mma.sync.
// BM=128, BK=64. MODE: 0=K1 (bias+qscale), 1=K2, 2=K4 (BN=64), 3=K5 (bias).
// 256 threads = 8 warps. BN=128: warps 2x4 (64x32 tile). BN=64: 4x2 (32x32).
// MMA issue is TERM-MAJOR: all (i,j) tiles for AhBh, then AhBl, then AlBh --
// 16 independent accumulator chains between reuses of the same acc.
// ---------------------------------------------------------------------------
template <int MODE>
__global__ __launch_bounds__(256, 1)
void tc_gemm(const float* __restrict__ A, const float* __restrict__ B,
             const float* __restrict__ bias, float* __restrict__ C)
{
    constexpr int BN    = (MODE == 2) ? 64 : 128;
    constexpr int K_TOT = (MODE == 1) ? 64 : (MODE == 2) ? 1024 : 768;
    constexpr int LDA   = (MODE == 0) ? CDIM : (MODE == 1) ? QKVC : (MODE == 2) ? SEQ : CDIM;
    constexpr int LDB   = (MODE == 1) ? QKVC : (MODE == 2) ? SEQ : CDIM;
    constexpr int LDC   = (MODE == 0) ? QKVC : (MODE == 1) ? SEQ : CDIM;
    constexpr int NITER = K_TOT / 64;
    constexpr int WM    = (MODE == 2) ? 2 : 4;      // m16 frags per warp
    constexpr int AREG  = 8;                         // float4 per thread (A tile)
    constexpr int BREG  = BN / 16;                   // float4 per thread (B tile)
    constexpr int OFF_AL = 16384;
    constexpr int OFF_BH = 32768;
    constexpr int OFF_BL = 32768 + BN * 128;
    constexpr int STAGE  = 32768 + 2 * BN * 128;

    extern __shared__ char smem[];
    const uint32_t smem_base = smem_to_u32(smem);
    const int tid  = threadIdx.x;
    const int warp = tid >> 5;
    const int lane = tid & 31;
    const int wmBase = (MODE == 2) ? (warp >> 1) * 32 : (warp & 1) * 64;
    const int wnBase = (MODE == 2) ? (warp & 1) * 32 : (warp >> 1) * 32;

    const int row0 = blockIdx.y * 128;
    const int col0 = blockIdx.x * BN;
    const int z = blockIdx.z;

    size_t aOff = 0, bOff = 0, cOff = 0;
    if (MODE == 1) {
        const int b = z / HEADS, h = z % HEADS;
        aOff = (size_t)b * SEQ * QKVC + (size_t)h * HDIM;
        bOff = aOff + CDIM;
        cOff = (size_t)z * SEQ * SEQ;
    } else if (MODE == 2) {
        aOff = (size_t)z * SEQ * SEQ;
        bOff = (size_t)z * HDIM * SEQ;
        cOff = (size_t)(z / HEADS) * SEQ * CDIM + (size_t)(z % HEADS) * HDIM;
    }
    const float* Ap = A + aOff;
    const float* Bp = B + bOff;
    float* Cp = C + cOff;

    float acc[WM][4][4];
#pragma unroll
    for (int i = 0; i < WM; i++)
#pragma unroll
        for (int j = 0; j < 4; j++)
#pragma unroll
            for (int e = 0; e < 4; e++) acc[i][j][e] = 0.0f;

    float4 aR[AREG], bR[BREG];

    auto load_gmem = [&](int k0) {
#pragma unroll
        for (int l = 0; l < AREG; l++) {
            const int g = tid + l * 256;
            aR[l] = *(const float4*)&Ap[(size_t)(row0 + (g >> 4)) * LDA + k0 + (g & 15) * 4];
        }
#pragma unroll
        for (int l = 0; l < BREG; l++) {
            const int g = tid + l * 256;
            bR[l] = *(const float4*)&Bp[(size_t)(col0 + (g >> 4)) * LDB + k0 + (g & 15) * 4];
        }
    };
    auto store_smem = [&](int p) {
        char* base = smem + p * STAGE;
#pragma unroll
        for (int l = 0; l < AREG; l++) {
            const int g = tid + l * 256;
            split_store_h(aR[l], base, base + OFF_AL, (g >> 4) * 128 + (g & 15) * 8);
        }
#pragma unroll
        for (int l = 0; l < BREG; l++) {
            const int g = tid + l * 256;
            split_store_h(bR[l], base + OFF_BH, base + OFF_BL, (g >> 4) * 128 + (g & 15) * 8);
        }
    };
    auto compute = [&](int p, int kkBeg, int kkEnd) {
        const uint32_t sb = smem_base + p * STAGE;
        const int r = lane & 7, g = lane >> 3;
        for (int kk = kkBeg; kk < kkEnd; kk++) {
            uint32_t ah[WM][4], al[WM][4];
#pragma unroll
            for (int i = 0; i < WM; i++) {
                const int row = wmBase + i * 16 + (g & 1) * 8 + r;
                int off = row * 128 + kk * 32 + (g >> 1) * 16;
                off ^= (off >> 3) & 0x70;
                LDSM4(ah[i][0], ah[i][1], ah[i][2], ah[i][3], sb + off);
                LDSM4(al[i][0], al[i][1], al[i][2], al[i][3], sb + OFF_AL + off);
            }
            uint32_t bh[4][2], bl[4][2];
#pragma unroll
            for (int jp = 0; jp < 2; jp++) {
                const int n = wnBase + jp * 16 + (g >> 1) * 8 + r;
                int off = n * 128 + kk * 32 + (g & 1) * 16;
                off ^= (off >> 3) & 0x70;
                LDSM4(bh[2 * jp][0], bh[2 * jp][1], bh[2 * jp + 1][0], bh[2 * jp + 1][1],
                      sb + OFF_BH + off);
                LDSM4(bl[2 * jp][0], bl[2 * jp][1], bl[2 * jp + 1][0], bl[2 * jp + 1][1],
                      sb + OFF_BL + off);
            }
            // term-major issue: 16 independent acc chains between reuses
#pragma unroll
            for (int i = 0; i < WM; i++)
#pragma unroll
                for (int j = 0; j < 4; j++)
                    MMA16816(acc[i][j], ah[i], bh[j]);
#pragma unroll
            for (int i = 0; i < WM; i++)
#pragma unroll
                for (int j = 0; j < 4; j++)
                    MMA16816(acc[i][j], ah[i], bl[j]);
#pragma unroll
            for (int i = 0; i < WM; i++)
#pragma unroll
                for (int j = 0; j < 4; j++)
                    MMA16816(acc[i][j], al[i], bh[j]);
        }
    };

    load_gmem(0);
    store_smem(0);
    __syncthreads();

    for (int it = 0; it < NITER; it++) {
        const int p = it & 1;
        const bool more = (it + 1 < NITER);
        if (more) load_gmem((it + 1) * 64);
        compute(p, 0, 2);
        if (more) store_smem(p ^ 1);
        compute(p, 2, 4);
        __syncthreads();
    }

    // epilogue: acc -> gmem fp32 (+bias, +qscale)
    const int qr = lane >> 2;            // 0..7
    const int qc = (lane & 3) * 2;       // 0,2,4,6
#pragma unroll
    for (int i = 0; i < WM; i++) {
#pragma unroll
        for (int j = 0; j < 4; j++) {
            const int gr = row0 + wmBase + i * 16 + qr;
            const int gc = col0 + wnBase + j * 8 + qc;
            float v0 = acc[i][j][0], v1 = acc[i][j][1];
            float v2 = acc[i][j][2], v3 = acc[i][j][3];
            if (MODE == 0 || MODE == 3) {
                const float b0 = bias[gc], b1 = bias[gc + 1];
                v0 += b0; v1 += b1; v2 += b0; v3 += b1;
            }
            if (MODE == 0) {
                if (gc < CDIM)     { v0 *= 0.125f; v2 *= 0.125f; }
                if (gc + 1 < CDIM) { v1 *= 0.125f; v3 *= 0.125f; }
            }
            *(float2*)&Cp[(size_t)gr * LDC + gc]       = make_float2(v0, v1);
            *(float2*)&Cp[(size_t)(gr + 8) * LDC + gc] = make_float2(v2, v3);
        }
    }
}

// ---------------------------------------------------------------------------
// Transposes (fp32)
// ---------------------------------------------------------------------------
__global__ void transpose_k(const float* __restrict__ in, float* __restrict__ out,
                            int rows, int cols)
{
    __shared__ float t[32][33];
    const int x = blockIdx.x * 32 + threadIdx.x;
    const int y0 = blockIdx.y * 32;
#pragma unroll
    for (int j = threadIdx.y; j < 32; j += 8)
        t[j][threadIdx.x] = in[(size_t)(y0 + j) * cols + x];
    __syncthreads();
    const int x2 = y0 + threadIdx.x;
    const int y2 = blockIdx.x * 32;
#pragma unroll
    for (int j = threadIdx.y; j < 32; j += 8)
        out[(size_t)(y2 + j) * rows + x2] = t[threadIdx.x][j];
}

__global__ void vt_kernel(const float* __restrict__ qkv, float* __restrict__ vt)
{
    __shared__ float t[32][33];
    const int z = blockIdx.z;
    const int b = z / HEADS, h = z % HEADS;
    const float* in = qkv + (size_t)b * SEQ * QKVC + 2 * CDIM + (size_t)h * HDIM;
    const int m0 = blockIdx.x * 32, d0 = blockIdx.y * 32;
#pragma unroll
    for (int j = threadIdx.y; j < 32; j += 8)
        t[j][threadIdx.x] = in[(size_t)(m0 + j) * QKVC + d0 + threadIdx.x];
    __syncthreads();
    float* outp = vt + (size_t)z * HDIM * SEQ;
#pragma unroll
    for (int j = threadIdx.y; j < 32; j += 8)
        outp[(size_t)(d0 + j) * SEQ + m0 + threadIdx.x] = t[threadIdx.x][j];
}

// ---------------------------------------------------------------------------
// K3 (fp32, register-resident): per (b,n): mix1 -> softmax -> mix2 -> attn
// ---------------------------------------------------------------------------
__global__ __launch_bounds__(256)
void mix_softmax_kernel(const float* __restrict__ logits,
                        const float* __restrict__ W_l, const float* __restrict__ b_l,
                        const float* __restrict__ W_w, const float* __restrict__ b_w,
                        float* __restrict__ attn_out)
{
    __shared__ float swl[HEADS * HEADS], sww[HEADS * HEADS];
    __shared__ float sbl[HEADS], sbw[HEADS];
    __shared__ float red[HEADS][8];

    const int tid  = threadIdx.x;
    const int lane = tid & 31;
    const int warp = tid >> 5;
    const int bn = blockIdx.x;
    const int b = bn >> 10;
    const int n = bn & (SEQ - 1);

    if (tid < HEADS * HEADS) { swl[tid] = W_l[tid]; sww[tid] = W_w[tid]; }
    if (tid < HEADS) { sbl[tid] = b_l[tid]; sbw[tid] = b_w[tid]; }
    __syncthreads();

    const float* lb = logits + ((size_t)b * HEADS * SEQ + n) * SEQ + tid * 4;
    float4 l[HEADS];
#pragma unroll
    for (int h = 0; h < HEADS; h++)
        l[h] = *(const float4*)&lb[(size_t)h * SEQ * SEQ];

    float4 m1[HEADS];
#pragma unroll
    for (int k = 0; k < HEADS; k++) {
        float bk = sbl[k];
        float4 a = make_float4(bk, bk, bk, bk);
#pragma unroll
        for (int h = 0; h < HEADS; h++) {
            const float w = swl[h * HEADS + k];
            a.x = fmaf(l[h].x, w, a.x);
            a.y = fmaf(l[h].y, w, a.y);
            a.z = fmaf(l[h].z, w, a.z);
            a.w = fmaf(l[h].w, w, a.w);
        }
        m1[k] = a;
    }

    float rowmax[HEADS];
#pragma unroll
    for (int k = 0; k < HEADS; k++) {
        float v = fmaxf(fmaxf(m1[k].x, m1[k].y), fmaxf(m1[k].z, m1[k].w));
#pragma unroll
        for (int o = 16; o > 0; o >>= 1) v = fmaxf(v, __shfl_xor_sync(0xffffffff, v, o));
        if (lane == 0) red[k][warp] = v;
    }
    __syncthreads();
#pragma unroll
    for (int k = 0; k < HEADS; k++) {
        float v = red[k][0];
#pragma unroll
        for (int w = 1; w < 8; w++) v = fmaxf(v, red[k][w]);
        rowmax[k] = v;
    }
    __syncthreads();

    float inv[HEADS];
#pragma unroll
    for (int k = 0; k < HEADS; k++) {
        m1[k].x = __expf(m1[k].x - rowmax[k]);
        m1[k].y = __expf(m1[k].y - rowmax[k]);
        m1[k].z = __expf(m1[k].z - rowmax[k]);
        m1[k].w = __expf(m1[k].w - rowmax[k]);
        float s = (m1[k].x + m1[k].y) + (m1[k].z + m1[k].w);
#pragma unroll
        for (int o = 16; o > 0; o >>= 1) s += __shfl_xor_sync(0xffffffff, s, o);
        if (lane == 0) red[k][warp] = s;
    }
    __syncthreads();
#pragma unroll
    for (int k = 0; k < HEADS; k++) {
        float s = red[k][0];
#pragma unroll
        for (int w = 1; w < 8; w++) s += red[k][w];
        inv[k] = 1.0f / s;
    }

#pragma unroll
    for (int h = 0; h < HEADS; h++) {
        m1[h].x *= inv[h]; m1[h].y *= inv[h];
        m1[h].z *= inv[h]; m1[h].w *= inv[h];
    }

    float* ob = attn_out + ((size_t)b * HEADS * SEQ + n) * SEQ + tid * 4;
#pragma unroll
    for (int k = 0; k < HEADS; k++) {
        float bk = sbw[k];
        float4 a = make_float4(bk, bk, bk, bk);
#pragma unroll
        for (int h = 0; h < HEADS; h++) {
            const float w = sww[h * HEADS + k];
            a.x = fmaf(m1[h].x, w, a.x);
            a.y = fmaf(m1[h].y, w, a.y);
            a.z = fmaf(m1[h].z, w, a.z);
            a.w = fmaf(m1[h].w, w, a.w);
        }
        *(float4*)&ob[(size_t)k * SEQ * SEQ] = a;
    }
}

// ---------------------------------------------------------------------------
extern "C" void kernel_launch(void* const* d_in, const int* in_sizes, int n_in,
                              void* d_out, int out_size)
{
    const float* x      = (const float*)d_in[0];
    const float* W_qkv  = (const float*)d_in[1];
    const float* b_qkv  = (const float*)d_in[2];
    const float* W_l    = (const float*)d_in[3];
    const float* b_l    = (const float*)d_in[4];
    const float* W_w    = (const float*)d_in[5];
    const float* b_w    = (const float*)d_in[6];
    const float* W_proj = (const float*)d_in[7];
    const float* b_proj = (const float*)d_in[8];

    float* out  = (float*)d_out;
    float* attn = out + OUT_ELEMS;

    float *qkv_p, *logits_p, *ctx_p, *wqkvt_p, *wprojt_p, *vt_p;
    cudaGetSymbolAddress((void**)&qkv_p, g_qkv);
    cudaGetSymbolAddress((void**)&logits_p, g_logits);
    cudaGetSymbolAddress((void**)&ctx_p, g_ctx);
    cudaGetSymbolAddress((void**)&wqkvt_p, g_wqkvt);
    cudaGetSymbolAddress((void**)&wprojt_p, g_wprojt);
    cudaGetSymbolAddress((void**)&vt_p, g_vt);

    const int smemBig = 2 * (32768 + 2 * 128 * 128);  // 131072 (BN=128, 2 stages)
    const int smemK2  = 32768 + 2 * 128 * 128;        //  65536 (single chunk)
    const int smemK4  = 2 * (32768 + 2 * 64 * 128);   //  98304 (BN=64)
    cudaFuncSetAttribute(tc_gemm<0>, cudaFuncAttributeMaxDynamicSharedMemorySize, smemBig);
    cudaFuncSetAttribute(tc_gemm<1>, cudaFuncAttributeMaxDynamicSharedMemorySize, smemK2);
    cudaFuncSetAttribute(tc_gemm<2>, cudaFuncAttributeMaxDynamicSharedMemorySize, smemK4);
    cudaFuncSetAttribute(tc_gemm<3>, cudaFuncAttributeMaxDynamicSharedMemorySize, smemBig);

    // P1/P2: weight transposes -> [N][K]
    transpose_k<<<dim3(QKVC / 32, CDIM / 32), dim3(32, 8)>>>(W_qkv, wqkvt_p, CDIM, QKVC);
    transpose_k<<<dim3(CDIM / 32, CDIM / 32), dim3(32, 8)>>>(W_proj, wprojt_p, CDIM, CDIM);

    // K1: qkv = x @ W_qkv^T' + b (q scaled)
    tc_gemm<0><<<dim3(QKVC / 128, TOKS / 128, 1), 256, smemBig>>>(x, wqkvt_p, b_qkv, qkv_p);

    // P3: v transpose -> vt[bh][d][m]
    vt_kernel<<<dim3(SEQ / 32, HDIM / 32, BATCH * HEADS), dim3(32, 8)>>>(qkv_p, vt_p);

    // K2: logits = q @ k^T per (b,h)
    tc_gemm<1><<<dim3(SEQ / 128, SEQ / 128, BATCH * HEADS), 256, smemK2>>>(
        qkv_p, qkv_p, nullptr, logits_p);

    // K3: mix -> softmax -> mix -> attn output
    mix_softmax_kernel<<<TOKS, 256>>>(logits_p, W_l, b_l, W_w, b_w, attn);

    // K4: ctx = attn @ vt^T per (b,h)
    tc_gemm<2><<<dim3(1, SEQ / 128, BATCH * HEADS), 256, smemK4>>>(
        attn, vt_p, nullptr, ctx_p);

    // K5: out = ctx @ W_proj^T' + b
    tc_gemm<3><<<dim3(CDIM / 128, TOKS / 128, 1), 256, smemBig>>>(
        ctx_p, wprojt_p, b_proj, out);
}